// round 16
// baseline (speedup 1.0000x reference)
#include <cuda_runtime.h>
#include <cuda_fp16.h>
#include <cstdint>
#include <mma.h>
#include <math.h>

using namespace nvcuda;

#define NODES_MAX 50000
#define EDGES_MAX 800000
#define GRAPHS_MAX 1024

// ---------------- scratch (device globals) ------------------------------------
__device__ int    g_eidx[2 * EDGES_MAX];
__device__ int    g_batch[NODES_MAX];
__device__ int    g_deg[NODES_MAX];
__device__ int    g_rowptr[NODES_MAX + 1];
__device__ int    g_bsum[256];
__device__ int    g_cur[NODES_MAX];
__device__ int    g_col[EDGES_MAX];
__device__ int    g_flag[1];
__device__ float  g_dinv[NODES_MAX];
__device__ __half g_xs0[(size_t)NODES_MAX * 64];
__device__ __half g_A1 [(size_t)NODES_MAX * 64];
__device__ __half g_A2 [(size_t)NODES_MAX * 256];   // [z2 | x1]
__device__ __half g_xs1[(size_t)NODES_MAX * 128];
__device__ __half g_A3 [(size_t)NODES_MAX * 512];   // [z3 | x2]
__device__ __half g_xs2[(size_t)NODES_MAX * 256];
__device__ __half g_x3 [(size_t)NODES_MAX * 256];
__device__ float  g_work[(size_t)NODES_MAX * 256];  // attn logits (fp32!)
__device__ __half g_w1r[64 * 128];
__device__ __half g_w2s[256 * 256];                 // [W2 ; Wr1]
__device__ __half g_w3s[512 * 256];                 // [W3 ; Wr2]
__device__ __half g_wattn[256 * 256];
__device__ __half g_fph [1024 * 2048];
__device__ __half g_wfph[2048 * 256];
__device__ __half g_fgp [1024 * 192];
__device__ __half g_wfgp[192 * 256];
__device__ float  g_fp[GRAPHS_MAX * 256];
__device__ float  g_fg[GRAPHS_MAX * 256];

__device__ __forceinline__ void cp16(uint32_t dst, const void* src, bool pred) {
    int bytes = pred ? 16 : 0;
    asm volatile("cp.async.cg.shared.global [%0], [%1], 16, %2;\n"
                 :: "r"(dst), "l"(src), "r"(bytes));
}
__device__ __forceinline__ void cp_commit() { asm volatile("cp.async.commit_group;\n"); }
__device__ __forceinline__ void cp_wait0()  { asm volatile("cp.async.wait_group 0;\n"); }
__device__ __forceinline__ void cp_wait1g() { asm volatile("cp.async.wait_group 1;\n"); }
__device__ __forceinline__ void cp_wait2g() { asm volatile("cp.async.wait_group 2;\n"); }

// ---------------- dtype detect ---------------------------------------------------
__global__ void detect_kernel(const unsigned int* __restrict__ w, int* __restrict__ flag) {
    int t = threadIdx.x;
    unsigned int v = w[2 * t + 1] | w[2 * (t + 32) + 1] | w[2 * (t + 64) + 1] | w[2 * (t + 96) + 1];
    unsigned int nz = __ballot_sync(0xFFFFFFFFu, v != 0u);
    if (t == 0) *flag = (nz == 0u) ? 1 : 0;
}

__global__ void cvt_all_kernel(const void* __restrict__ eraw, int E,
                               const void* __restrict__ braw, int n,
                               const int* __restrict__ flag, int* __restrict__ eidx,
                               int* __restrict__ deg, int* __restrict__ batch) {
    int i = blockIdx.x * blockDim.x + threadIdx.x;
    bool f = (*flag != 0);
    if (i < E) {
        int s, d;
        if (f) {
            s = (int)((const long long*)eraw)[i];
            d = (int)((const long long*)eraw)[E + i];
        } else {
            s = ((const int*)eraw)[i];
            d = ((const int*)eraw)[E + i];
        }
        eidx[i] = s;
        eidx[E + i] = d;
        atomicAdd(&deg[d], 1);
    } else {
        int j = i - E;
        if (j < n) {
            batch[j] = f ? (int)((const long long*)braw)[j] : ((const int*)braw)[j];
        }
    }
}

// ---------------- prep kernel ----------------------------------------------------
__global__ void prep_kernel(
    const float* __restrict__ W1, const float* __restrict__ W2, const float* __restrict__ Wr1,
    const float* __restrict__ W3, const float* __restrict__ Wr2, const float* __restrict__ attn_W,
    const float* __restrict__ fpf, const float* __restrict__ Wfp,
    const float* __restrict__ fgf, const float* __restrict__ Wfg,
    __half* __restrict__ w1r, __half* __restrict__ w2s, __half* __restrict__ w3s,
    __half* __restrict__ wattn, __half* __restrict__ fph, __half* __restrict__ wfph,
    __half* __restrict__ fgp, __half* __restrict__ wfgp)
{
    int j = blockIdx.x * blockDim.x + threadIdx.x;
    if (j < 8192) { w1r[j] = __float2half_rn(W1[j]); return; }
    j -= 8192;
    if (j < 65536) {
        int k = j >> 8, c = j & 255;
        float v = (k < 128) ? W2[k * 256 + c] : Wr1[(k - 128) * 256 + c];
        w2s[j] = __float2half_rn(v); return;
    }
    j -= 65536;
    if (j < 131072) {
        int k = j >> 8, c = j & 255;
        float v = (k < 256) ? W3[k * 256 + c] : Wr2[(k - 256) * 256 + c];
        w3s[j] = __float2half_rn(v); return;
    }
    j -= 131072;
    if (j < 65536) { wattn[j] = __float2half_rn(attn_W[j]); return; }
    j -= 65536;
    if (j < 2097152) { fph[j] = __float2half_rn(fpf[j]); return; }
    j -= 2097152;
    if (j < 524288) { wfph[j] = __float2half_rn(Wfp[j]); return; }
    j -= 524288;
    if (j < 196608) {
        int r = j / 192, c = j % 192;
        fgp[j] = __float2half_rn(c < 167 ? fgf[r * 167 + c] : 0.f); return;
    }
    j -= 196608;
    if (j < 49152) {
        int k = j >> 8, c = j & 255;
        wfgp[j] = __float2half_rn(k < 167 ? Wfg[k * 256 + c] : 0.f); return;
    }
}
#define PREP_TOTAL (8192 + 65536 + 131072 + 65536 + 2097152 + 524288 + 196608 + 49152)

// ---------------- scan phase 1: block sums + dinv + xs0 = half(x*dinv) ----------
__global__ void scan_p1_kernel(const int* __restrict__ deg, float* __restrict__ dinv,
                               int* __restrict__ bsum,
                               const float* __restrict__ x, __half* __restrict__ xs0, int n) {
    __shared__ int red[256];
    int t = threadIdx.x;
    int i = blockIdx.x * 256 + t;
    int v = 0;
    if (i < n) { v = deg[i]; dinv[i] = rsqrtf((float)v + 1.0f); }
    red[t] = v;
    __syncthreads();
    #pragma unroll
    for (int off = 128; off > 0; off >>= 1) {
        if (t < off) red[t] += red[t + off];
        __syncthreads();
    }
    if (t == 0) bsum[blockIdx.x] = red[0];

    int base = blockIdx.x * 256;
    int lane = t & 31, w = t >> 5;
    for (int nn = w; nn < 256; nn += 8) {
        int node = base + nn;
        if (node >= n) break;
        float dvn = rsqrtf((float)deg[node] + 1.0f);
        float2 xv = ((const float2*)(x + (size_t)node * 64))[lane];
        ((half2*)(xs0 + (size_t)node * 64))[lane] =
            __floats2half2_rn(xv.x * dvn, xv.y * dvn);
    }
}

__global__ void scan_p2_kernel(const int* __restrict__ deg, const int* __restrict__ bsum,
                               int* __restrict__ rowptr, int* __restrict__ cur, int n, int nb) {
    __shared__ int s[256];
    __shared__ int pre[256];
    int t = threadIdx.x;

    pre[t] = (t < nb) ? bsum[t] : 0;
    __syncthreads();
    #pragma unroll
    for (int off = 1; off < 256; off <<= 1) {
        int v = (t >= off) ? pre[t - off] : 0;
        __syncthreads();
        pre[t] += v;
        __syncthreads();
    }
    int blockOff = (blockIdx.x == 0) ? 0 : pre[blockIdx.x - 1];

    int i = blockIdx.x * 256 + t;
    int v = (i < n) ? deg[i] : 0;
    s[t] = v;
    __syncthreads();
    #pragma unroll
    for (int off = 1; off < 256; off <<= 1) {
        int u = (t >= off) ? s[t - off] : 0;
        __syncthreads();
        s[t] += u;
        __syncthreads();
    }
    if (i < n) { rowptr[i] = blockOff + s[t] - v; cur[i] = 0; }
    if (blockIdx.x == gridDim.x - 1 && t == 255) rowptr[n] = blockOff + s[255];
}

__global__ void fill_csr_kernel(const int* __restrict__ src, const int* __restrict__ dst, int E,
                                const int* __restrict__ rowptr, int* __restrict__ cur,
                                int* __restrict__ col) {
    int i = blockIdx.x * blockDim.x + threadIdx.x;
    if (i >= E) return;
    int d = dst[i];
    int pos = rowptr[d] + atomicAdd(&cur[d], 1);
    col[pos] = src[i];
}

// ---------------- input-space aggregation (fp16 gather, fp32 acc) --------------
template <int C>
__global__ void aggregate_kernel(const __half* __restrict__ xs,
                                 const int* __restrict__ rowptr, const int* __restrict__ col,
                                 const float* __restrict__ dinv,
                                 __half* __restrict__ out, int ldo, int n)
{
    int node = (blockIdx.x * blockDim.x + threadIdx.x) >> 5;
    if (node >= n) return;
    int lane = threadIdx.x & 31;
    constexpr int F  = C / 32;
    constexpr int HV = F / 2;

    float acc[F];

    auto loadRow = [&](const __half* p, half2* h) {
        if constexpr (F == 2) {
            *(uint32_t*)h = *(const uint32_t*)p;
        } else if constexpr (F == 4) {
            *(uint2*)h = *(const uint2*)p;
        } else {
            *(uint4*)h = *(const uint4*)p;
        }
    };
    auto accRow = [&](const half2* h) {
        #pragma unroll
        for (int j = 0; j < HV; j++) {
            float2 f = __half22float2(h[j]);
            acc[2 * j] += f.x; acc[2 * j + 1] += f.y;
        }
    };

    {
        half2 h[HV];
        loadRow(xs + (size_t)node * C + lane * F, h);
        #pragma unroll
        for (int j = 0; j < HV; j++) {
            float2 f = __half22float2(h[j]);
            acc[2 * j] = f.x; acc[2 * j + 1] = f.y;
        }
    }

    int s = rowptr[node], e = rowptr[node + 1];
    int k = s;
    for (; k + 3 < e; k += 4) {
        half2 h0[HV], h1[HV], h2[HV], h3[HV];
        loadRow(xs + (size_t)col[k + 0] * C + lane * F, h0);
        loadRow(xs + (size_t)col[k + 1] * C + lane * F, h1);
        loadRow(xs + (size_t)col[k + 2] * C + lane * F, h2);
        loadRow(xs + (size_t)col[k + 3] * C + lane * F, h3);
        accRow(h0); accRow(h1); accRow(h2); accRow(h3);
    }
    for (; k < e; k++) {
        half2 h[HV];
        loadRow(xs + (size_t)col[k] * C + lane * F, h);
        accRow(h);
    }

    float dv = dinv[node];
    half2* orow = (half2*)(out + (size_t)node * ldo + lane * F);
    #pragma unroll
    for (int j = 0; j < HV; j++)
        orow[j] = __floats2half2_rn(dv * acc[2 * j], dv * acc[2 * j + 1]);
}

// ---------------- fp16 GEMM: 8 warps, warp tile 64x32, BK=64, 3-stage ----------
#define GEMM_AS 9216          // halfs per A stage (128*72)
#define GEMM_BS 8704          // halfs per B stage (64*136)
#define GEMM_STAGE (GEMM_AS + GEMM_BS)
#define GEMM_NSTG 3
#define GEMM_SMEM (GEMM_NSTG * GEMM_STAGE * 2)   // 107520 bytes

__global__ __launch_bounds__(256) void gemm_h_kernel(
    const __half* __restrict__ A, const __half* __restrict__ B,
    __half* __restrict__ Ch, float* __restrict__ Cf,
    int M, int N, int K, int ldc, int kChunk, int atomicOut,
    const float* __restrict__ bias1, const float* __restrict__ bias2,
    __half* __restrict__ C2, int ld2, const float* __restrict__ dinv)
{
    extern __shared__ __half sm[];
    const int BK = 64;
    const int LDA = 72, LDB = 136;

    int tid  = threadIdx.x;
    int lane = tid & 31;
    int warp = tid >> 5;
    int warpM = (warp >> 2) * 64;
    int warpN = (warp & 3) * 32;
    int rowBase = blockIdx.y * 128;
    int colBase = blockIdx.x * 128;

    int kStart = blockIdx.z * kChunk;
    int kEnd   = min(K, kStart + kChunk);
    int ntiles = (kEnd - kStart) / BK;

    wmma::fragment<wmma::accumulator, 16, 16, 16, float> acc[4][2];
    #pragma unroll
    for (int m = 0; m < 4; m++)
        #pragma unroll
        for (int n = 0; n < 2; n++) wmma::fill_fragment(acc[m][n], 0.0f);

    uint32_t smBase = (uint32_t)__cvta_generic_to_shared(sm);

    auto issue = [&](int t, int s) {
        int k0 = kStart + t * BK;
        uint32_t asB = smBase + (uint32_t)(s * GEMM_STAGE) * 2u;
        uint32_t bsB = asB + (uint32_t)GEMM_AS * 2u;
        #pragma unroll
        for (int h = 0; h < 4; h++) {
            int c = tid + h * 256;
            int row = c >> 3, q = c & 7;
            int r = rowBase + row;
            bool ok = (r < M);
            const __half* src = A + (size_t)(ok ? r : 0) * K + k0 + q * 8;
            cp16(asB + (uint32_t)(row * LDA + q * 8) * 2u, src, ok);
        }
        #pragma unroll
        for (int h = 0; h < 4; h++) {
            int c = tid + h * 256;
            int row = c >> 4, q = c & 15;
            const __half* src = B + (size_t)(k0 + row) * N + colBase + q * 8;
            cp16(bsB + (uint32_t)(row * LDB + q * 8) * 2u, src, true);
        }
    };

    issue(0, 0);
    cp_commit();
    if (ntiles > 1) { issue(1, 1); cp_commit(); }

    int s = 0;
    for (int t = 0; t < ntiles; t++) {
        if (t + 1 < ntiles) cp_wait1g(); else cp_wait0();
        __syncthreads();
        if (t + 2 < ntiles) {
            int s2 = s + 2; if (s2 >= GEMM_NSTG) s2 -= GEMM_NSTG;
            issue(t + 2, s2);
            cp_commit();
        }

        const __half* as = sm + s * GEMM_STAGE;
        const __half* bs = as + GEMM_AS;
        #pragma unroll
        for (int kk = 0; kk < BK; kk += 16) {
            wmma::fragment<wmma::matrix_a, 16, 16, 16, __half, wmma::row_major> af[4];
            wmma::fragment<wmma::matrix_b, 16, 16, 16, __half, wmma::row_major> bf[2];
            #pragma unroll
            for (int m = 0; m < 4; m++)
                wmma::load_matrix_sync(af[m], as + (warpM + 16 * m) * LDA + kk, LDA);
            #pragma unroll
            for (int n = 0; n < 2; n++)
                wmma::load_matrix_sync(bf[n], bs + kk * LDB + warpN + 16 * n, LDB);
            #pragma unroll
            for (int m = 0; m < 4; m++)
                #pragma unroll
                for (int n = 0; n < 2; n++)
                    wmma::mma_sync(acc[m][n], af[m], bf[n], acc[m][n]);
        }
        if (++s >= GEMM_NSTG) s = 0;
    }
    __syncthreads();

    float* es = (float*)sm + warp * 320;
    #pragma unroll
    for (int m = 0; m < 4; m++) {
        #pragma unroll
        for (int n = 0; n < 2; n++) {
            wmma::store_matrix_sync(es, acc[m][n], 20, wmma::mem_row_major);
            __syncwarp();
            #pragma unroll
            for (int i = 0; i < 2; i++) {
                int r  = i * 8 + (lane >> 2);
                int c4 = (lane & 3) * 4;
                int gr = rowBase + warpM + 16 * m + r;
                int gc = colBase + warpN + 16 * n + c4;
                if (gr < M) {
                    float4 v = *(float4*)(es + r * 20 + c4);
                    if (Cf) {
                        float* cp = Cf + (size_t)gr * ldc + gc;
                        if (atomicOut) {
                            atomicAdd(cp + 0, v.x); atomicAdd(cp + 1, v.y);
                            atomicAdd(cp + 2, v.z); atomicAdd(cp + 3, v.w);
                        } else {
                            *(float4*)cp = v;
                        }
                    } else {
                        if (bias1) {
                            v.x += bias1[gc]; v.y += bias1[gc + 1];
                            v.z += bias1[gc + 2]; v.w += bias1[gc + 3];
                        }
                        if (bias2) {
                            v.x += bias2[gc]; v.y += bias2[gc + 1];
                            v.z += bias2[gc + 2]; v.w += bias2[gc + 3];
                        }
                        v.x = fmaxf(v.x, 0.f); v.y = fmaxf(v.y, 0.f);
                        v.z = fmaxf(v.z, 0.f); v.w = fmaxf(v.w, 0.f);
                        half2 h0 = __floats2half2_rn(v.x, v.y);
                        half2 h1 = __floats2half2_rn(v.z, v.w);
                        half2* cp = (half2*)(Ch + (size_t)gr * ldc + gc);
                        cp[0] = h0; cp[1] = h1;
                        if (C2) {
                            float dv = dinv[gr];
                            float2 f0 = __half22float2(h0);
                            float2 f1 = __half22float2(h1);
                            half2* c2 = (half2*)(C2 + (size_t)gr * ld2 + gc);
                            c2[0] = __floats2half2_rn(dv * f0.x, dv * f0.y);
                            c2[1] = __floats2half2_rn(dv * f1.x, dv * f1.y);
                        }
                    }
                }
            }
            __syncwarp();
        }
    }
}

// ---------------- softmax * x3 pooled mean + final projection (fused) ----------
__device__ __forceinline__ int lowerb(const int* a, int n, int key) {
    int lo = 0, hi = n;
    while (lo < hi) { int mid = (lo + hi) >> 1; if (a[mid] < key) lo = mid + 1; else hi = mid; }
    return lo;
}

__global__ void pool_final_kernel(const float* __restrict__ logits, const __half* __restrict__ x3,
                                  const int* __restrict__ batch,
                                  const float* __restrict__ fpa, const float* __restrict__ fga,
                                  const float* __restrict__ bfp, const float* __restrict__ bfg,
                                  const float* __restrict__ Wfc, const float* __restrict__ bfc,
                                  float* __restrict__ out, int n)
{
    __shared__ float sred[8 * 256];
    __shared__ float fsum[8];
    int g = blockIdx.x;
    int lane = threadIdx.x & 31;
    int w = threadIdx.x >> 5;

    int start = lowerb(batch, n, g);
    int end   = lowerb(batch, n, g + 1);

    float acc[8];
    #pragma unroll
    for (int j = 0; j < 8; j++) acc[j] = 0.f;

    for (int node = start + w; node < end; node += 8) {
        const float4* lr = (const float4*)(logits + (size_t)node * 256 + lane * 8);
        float4 a0 = lr[0], a1 = lr[1];
        float a[8] = {a0.x, a0.y, a0.z, a0.w, a1.x, a1.y, a1.z, a1.w};
        float m = a[0];
        #pragma unroll
        for (int j = 1; j < 8; j++) m = fmaxf(m, a[j]);
        #pragma unroll
        for (int off = 16; off > 0; off >>= 1) m = fmaxf(m, __shfl_xor_sync(0xFFFFFFFFu, m, off));
        float s = 0.f;
        #pragma unroll
        for (int j = 0; j < 8; j++) { a[j] = __expf(a[j] - m); s += a[j]; }
        #pragma unroll
        for (int off = 16; off > 0; off >>= 1) s += __shfl_xor_sync(0xFFFFFFFFu, s, off);
        float inv = 1.f / s;

        half2 hx[4];
        *(uint4*)hx = *(const uint4*)(x3 + (size_t)node * 256 + lane * 8);
        #pragma unroll
        for (int j = 0; j < 4; j++) {
            float2 f = __half22float2(hx[j]);
            acc[2 * j]     += a[2 * j]     * inv * f.x;
            acc[2 * j + 1] += a[2 * j + 1] * inv * f.y;
        }
    }

    #pragma unroll
    for (int j = 0; j < 8; j++) sred[w * 256 + lane * 8 + j] = acc[j];
    __syncthreads();

    // per-thread: pooled value for feature t, then fused final projection
    int t = threadIdx.x;
    float v = 0.f;
    #pragma unroll
    for (int ww = 0; ww < 8; ww++) v += sred[ww * 256 + t];
    float invc = 1.f / fmaxf((float)(end - start), 1.f);
    size_t o = (size_t)g * 256 + t;
    float pv = v * invc
             + fmaxf(fpa[o] + bfp[t], 0.f)
             + fmaxf(fga[o] + bfg[t], 0.f);
    float term = pv * Wfc[t];

    // block reduction of 256 terms
    #pragma unroll
    for (int off = 16; off > 0; off >>= 1) term += __shfl_xor_sync(0xFFFFFFFFu, term, off);
    if (lane == 0) fsum[w] = term;
    __syncthreads();
    if (t == 0) {
        float ssum = 0.f;
        #pragma unroll
        for (int ww = 0; ww < 8; ww++) ssum += fsum[ww];
        out[g] = ssum + bfc[0];
    }
}

// ---------------- host launcher -------------------------------------------------
extern "C" void kernel_launch(void* const* d_in, const int* in_sizes, int n_in,
                              void* d_out, int out_size)
{
    const float* x    = (const float*)d_in[0];
    const void*  eraw = d_in[1];
    const void*  braw = d_in[2];
    const float* fpf  = (const float*)d_in[3];
    const float* fgf  = (const float*)d_in[4];
    const float* W1   = (const float*)d_in[5];  const float* b1  = (const float*)d_in[6];
    const float* W2   = (const float*)d_in[7];  const float* b2  = (const float*)d_in[8];
    const float* W3   = (const float*)d_in[9];  const float* b3  = (const float*)d_in[10];
    const float* Wr1  = (const float*)d_in[11]; const float* br1 = (const float*)d_in[12];
    const float* Wr2  = (const float*)d_in[13]; const float* br2 = (const float*)d_in[14];
    const float* Wfp  = (const float*)d_in[15]; const float* bfp = (const float*)d_in[16];
    const float* Wfg  = (const float*)d_in[17]; const float* bfg = (const float*)d_in[18];
    const float* attn_W = (const float*)d_in[19];
    const float* Wfc  = (const float*)d_in[20]; const float* bfc = (const float*)d_in[21];
    float* out = (float*)d_out;

    int N = in_sizes[0] / 64;
    int E = in_sizes[1] / 2;
    int B = in_sizes[3] / 2048;

    __half *xs0, *A1, *A2, *xs1, *A3, *xs2, *x3;
    __half *w1r, *w2s, *w3s, *wattn, *fph, *wfph, *fgp, *wfgp;
    float *work, *dinv, *fp, *fg;
    int *eidx, *batch, *deg, *rowptr, *bsum, *cur, *col, *flag;
    cudaGetSymbolAddress((void**)&eidx,   g_eidx);
    cudaGetSymbolAddress((void**)&batch,  g_batch);
    cudaGetSymbolAddress((void**)&deg,    g_deg);
    cudaGetSymbolAddress((void**)&rowptr, g_rowptr);
    cudaGetSymbolAddress((void**)&bsum,   g_bsum);
    cudaGetSymbolAddress((void**)&cur,    g_cur);
    cudaGetSymbolAddress((void**)&col,    g_col);
    cudaGetSymbolAddress((void**)&flag,   g_flag);
    cudaGetSymbolAddress((void**)&dinv,   g_dinv);
    cudaGetSymbolAddress((void**)&xs0,    g_xs0);
    cudaGetSymbolAddress((void**)&A1,     g_A1);
    cudaGetSymbolAddress((void**)&A2,     g_A2);
    cudaGetSymbolAddress((void**)&xs1,    g_xs1);
    cudaGetSymbolAddress((void**)&A3,     g_A3);
    cudaGetSymbolAddress((void**)&xs2,    g_xs2);
    cudaGetSymbolAddress((void**)&x3,     g_x3);
    cudaGetSymbolAddress((void**)&work,   g_work);
    cudaGetSymbolAddress((void**)&w1r,    g_w1r);
    cudaGetSymbolAddress((void**)&w2s,    g_w2s);
    cudaGetSymbolAddress((void**)&w3s,    g_w3s);
    cudaGetSymbolAddress((void**)&wattn,  g_wattn);
    cudaGetSymbolAddress((void**)&fph,    g_fph);
    cudaGetSymbolAddress((void**)&wfph,   g_wfph);
    cudaGetSymbolAddress((void**)&fgp,    g_fgp);
    cudaGetSymbolAddress((void**)&wfgp,   g_wfgp);
    cudaGetSymbolAddress((void**)&fp,     g_fp);
    cudaGetSymbolAddress((void**)&fg,     g_fg);

    static int attrSet = 0;
    if (!attrSet) {
        cudaFuncSetAttribute(gemm_h_kernel, cudaFuncAttributeMaxDynamicSharedMemorySize, GEMM_SMEM);
        attrSet = 1;
    }

    cudaMemsetAsync(deg, 0, N * sizeof(int));
    cudaMemsetAsync(fp,  0, (size_t)B * 256 * sizeof(float));

    // dtype detect + combined edge/batch conversion + degree
    detect_kernel<<<1, 32>>>((const unsigned int*)eraw, flag);
    cvt_all_kernel<<<(E + N + 255) / 256, 256>>>(eraw, E, braw, N, flag, eidx, deg, batch);
    const int* srcA = eidx;
    const int* dstA = eidx + E;

    // two-phase scan (dinv + xs0 fused in p1; bsum prefix + cur zero in p2)
    int nb = (N + 255) / 256;
    scan_p1_kernel<<<nb, 256>>>(deg, dinv, bsum, x, xs0, N);
    scan_p2_kernel<<<nb, 256>>>(deg, bsum, rowptr, cur, N, nb);
    fill_csr_kernel<<<(E + 255) / 256, 256>>>(srcA, dstA, E, rowptr, cur, col);

    prep_kernel<<<(PREP_TOTAL + 255) / 256, 256>>>(
        W1, W2, Wr1, W3, Wr2, attn_W, fpf, Wfp, fgf, Wfg,
        w1r, w2s, w3s, wattn, fph, wfph, fgp, wfgp);

    int aggBlocks = (N * 32 + 255) / 256;
    int gy = (N + 127) / 128;

    // fp / fg (fp16; fp split-K 8 with fp32 atomic accum; kChunk multiples of 64)
    gemm_h_kernel<<<dim3(2, (B + 127) / 128, 8), 256, GEMM_SMEM>>>(
        fph, wfph, nullptr, fp, B, 256, 2048, 256, 256, 1,
        nullptr, nullptr, nullptr, 0, nullptr);
    gemm_h_kernel<<<dim3(2, (B + 127) / 128, 1), 256, GEMM_SMEM>>>(
        fgp, wfgp, nullptr, fg, B, 256, 192, 256, 192, 0,
        nullptr, nullptr, nullptr, 0, nullptr);

    // Layer 1 (K=64)
    aggregate_kernel<64><<<aggBlocks, 256>>>(xs0, rowptr, col, dinv, A1, 64, N);
    gemm_h_kernel<<<dim3(1, gy), 256, GEMM_SMEM>>>(
        A1, w1r, A2 + 128, nullptr, N, 128, 64, 256, 64, 0,
        b1, nullptr, xs1, 128, dinv);

    // Layer 2 (K=256)
    aggregate_kernel<128><<<aggBlocks, 256>>>(xs1, rowptr, col, dinv, A2, 256, N);
    gemm_h_kernel<<<dim3(2, gy), 256, GEMM_SMEM>>>(
        A2, w2s, A3 + 256, nullptr, N, 256, 256, 512, 256, 0,
        b2, br1, xs2, 256, dinv);

    // Layer 3 (K=512)
    aggregate_kernel<256><<<aggBlocks, 256>>>(xs2, rowptr, col, dinv, A3, 512, N);
    gemm_h_kernel<<<dim3(2, gy), 256, GEMM_SMEM>>>(
        A3, w3s, x3, nullptr, N, 256, 512, 256, 512, 0,
        b3, br2, nullptr, 0, nullptr);

    // Attention logits (fp32 out, K=256)
    gemm_h_kernel<<<dim3(2, gy), 256, GEMM_SMEM>>>(
        x3, wattn, nullptr, work, N, 256, 256, 256, 256, 0,
        nullptr, nullptr, nullptr, 0, nullptr);

    // fused softmax-pool + final projection
    pool_final_kernel<<<B, 256>>>(work, x3, batch, fp, fg, bfp, bfg, Wfc, bfc, out, N);
}

// round 17
// speedup vs baseline: 1.0141x; 1.0141x over previous
#include <cuda_runtime.h>
#include <cuda_fp16.h>
#include <cstdint>
#include <mma.h>
#include <math.h>

using namespace nvcuda;

#define NODES_MAX 50000
#define EDGES_MAX 800000
#define GRAPHS_MAX 1024

// ---------------- scratch (device globals) ------------------------------------
__device__ int    g_eidx[2 * EDGES_MAX];
__device__ int    g_batch[NODES_MAX];
__device__ int    g_deg[NODES_MAX];
__device__ int    g_rowptr[NODES_MAX + 1];
__device__ int    g_bsum[256];
__device__ int    g_cur[NODES_MAX];
__device__ int    g_col[EDGES_MAX];
__device__ int    g_flag[1];
__device__ float  g_dinv[NODES_MAX];
__device__ __half g_xs0[(size_t)NODES_MAX * 64];
__device__ __half g_A1 [(size_t)NODES_MAX * 64];
__device__ __half g_A2 [(size_t)NODES_MAX * 256];   // [z2 | x1]
__device__ __half g_xs1[(size_t)NODES_MAX * 128];
__device__ __half g_A3 [(size_t)NODES_MAX * 512];   // [z3 | x2]
__device__ __half g_xs2[(size_t)NODES_MAX * 256];
__device__ __half g_x3 [(size_t)NODES_MAX * 256];
__device__ float  g_work[(size_t)NODES_MAX * 256];  // attn logits (fp32!)
__device__ __half g_w1r[64 * 128];
__device__ __half g_w2s[256 * 256];                 // [W2 ; Wr1]
__device__ __half g_w3s[512 * 256];                 // [W3 ; Wr2]
__device__ __half g_wattn[256 * 256];
__device__ __half g_fph [1024 * 2048];
__device__ __half g_wfph[2048 * 256];
__device__ __half g_fgp [1024 * 192];
__device__ __half g_wfgp[192 * 256];
__device__ float  g_fp[GRAPHS_MAX * 256];
__device__ float  g_fg[GRAPHS_MAX * 256];

__device__ __forceinline__ void cp16(uint32_t dst, const void* src, bool pred) {
    int bytes = pred ? 16 : 0;
    asm volatile("cp.async.cg.shared.global [%0], [%1], 16, %2;\n"
                 :: "r"(dst), "l"(src), "r"(bytes));
}
__device__ __forceinline__ void cp_commit() { asm volatile("cp.async.commit_group;\n"); }
__device__ __forceinline__ void cp_wait0()  { asm volatile("cp.async.wait_group 0;\n"); }
__device__ __forceinline__ void cp_wait1g() { asm volatile("cp.async.wait_group 1;\n"); }

// ---------------- dtype detect ---------------------------------------------------
__global__ void detect_kernel(const unsigned int* __restrict__ w, int* __restrict__ flag) {
    int t = threadIdx.x;
    unsigned int v = w[2 * t + 1] | w[2 * (t + 32) + 1] | w[2 * (t + 64) + 1] | w[2 * (t + 96) + 1];
    unsigned int nz = __ballot_sync(0xFFFFFFFFu, v != 0u);
    if (t == 0) *flag = (nz == 0u) ? 1 : 0;
}

__global__ void cvt_all_kernel(const void* __restrict__ eraw, int E,
                               const void* __restrict__ braw, int n,
                               const int* __restrict__ flag, int* __restrict__ eidx,
                               int* __restrict__ deg, int* __restrict__ batch) {
    int i = blockIdx.x * blockDim.x + threadIdx.x;
    bool f = (*flag != 0);
    if (i < E) {
        int s, d;
        if (f) {
            s = (int)((const long long*)eraw)[i];
            d = (int)((const long long*)eraw)[E + i];
        } else {
            s = ((const int*)eraw)[i];
            d = ((const int*)eraw)[E + i];
        }
        eidx[i] = s;
        eidx[E + i] = d;
        atomicAdd(&deg[d], 1);
    } else {
        int j = i - E;
        if (j < n) {
            batch[j] = f ? (int)((const long long*)braw)[j] : ((const int*)braw)[j];
        }
    }
}

// ---------------- prep kernel ----------------------------------------------------
__global__ void prep_kernel(
    const float* __restrict__ W1, const float* __restrict__ W2, const float* __restrict__ Wr1,
    const float* __restrict__ W3, const float* __restrict__ Wr2, const float* __restrict__ attn_W,
    const float* __restrict__ fpf, const float* __restrict__ Wfp,
    const float* __restrict__ fgf, const float* __restrict__ Wfg,
    __half* __restrict__ w1r, __half* __restrict__ w2s, __half* __restrict__ w3s,
    __half* __restrict__ wattn, __half* __restrict__ fph, __half* __restrict__ wfph,
    __half* __restrict__ fgp, __half* __restrict__ wfgp)
{
    int j = blockIdx.x * blockDim.x + threadIdx.x;
    if (j < 8192) { w1r[j] = __float2half_rn(W1[j]); return; }
    j -= 8192;
    if (j < 65536) {
        int k = j >> 8, c = j & 255;
        float v = (k < 128) ? W2[k * 256 + c] : Wr1[(k - 128) * 256 + c];
        w2s[j] = __float2half_rn(v); return;
    }
    j -= 65536;
    if (j < 131072) {
        int k = j >> 8, c = j & 255;
        float v = (k < 256) ? W3[k * 256 + c] : Wr2[(k - 256) * 256 + c];
        w3s[j] = __float2half_rn(v); return;
    }
    j -= 131072;
    if (j < 65536) { wattn[j] = __float2half_rn(attn_W[j]); return; }
    j -= 65536;
    if (j < 2097152) { fph[j] = __float2half_rn(fpf[j]); return; }
    j -= 2097152;
    if (j < 524288) { wfph[j] = __float2half_rn(Wfp[j]); return; }
    j -= 524288;
    if (j < 196608) {
        int r = j / 192, c = j % 192;
        fgp[j] = __float2half_rn(c < 167 ? fgf[r * 167 + c] : 0.f); return;
    }
    j -= 196608;
    if (j < 49152) {
        int k = j >> 8, c = j & 255;
        wfgp[j] = __float2half_rn(k < 167 ? Wfg[k * 256 + c] : 0.f); return;
    }
}
#define PREP_TOTAL (8192 + 65536 + 131072 + 65536 + 2097152 + 524288 + 196608 + 49152)

// ---------------- scan phase 1: block sums + dinv + xs0 = half(x*dinv) ----------
__global__ void scan_p1_kernel(const int* __restrict__ deg, float* __restrict__ dinv,
                               int* __restrict__ bsum,
                               const float* __restrict__ x, __half* __restrict__ xs0, int n) {
    __shared__ int red[256];
    int t = threadIdx.x;
    int i = blockIdx.x * 256 + t;
    int v = 0;
    if (i < n) { v = deg[i]; dinv[i] = rsqrtf((float)v + 1.0f); }
    red[t] = v;
    __syncthreads();
    #pragma unroll
    for (int off = 128; off > 0; off >>= 1) {
        if (t < off) red[t] += red[t + off];
        __syncthreads();
    }
    if (t == 0) bsum[blockIdx.x] = red[0];

    int base = blockIdx.x * 256;
    int lane = t & 31, w = t >> 5;
    for (int nn = w; nn < 256; nn += 8) {
        int node = base + nn;
        if (node >= n) break;
        float dvn = rsqrtf((float)deg[node] + 1.0f);
        float2 xv = ((const float2*)(x + (size_t)node * 64))[lane];
        ((half2*)(xs0 + (size_t)node * 64))[lane] =
            __floats2half2_rn(xv.x * dvn, xv.y * dvn);
    }
}

__global__ void scan_p2_kernel(const int* __restrict__ deg, const int* __restrict__ bsum,
                               int* __restrict__ rowptr, int* __restrict__ cur, int n, int nb) {
    __shared__ int s[256];
    __shared__ int pre[256];
    int t = threadIdx.x;

    pre[t] = (t < nb) ? bsum[t] : 0;
    __syncthreads();
    #pragma unroll
    for (int off = 1; off < 256; off <<= 1) {
        int v = (t >= off) ? pre[t - off] : 0;
        __syncthreads();
        pre[t] += v;
        __syncthreads();
    }
    int blockOff = (blockIdx.x == 0) ? 0 : pre[blockIdx.x - 1];

    int i = blockIdx.x * 256 + t;
    int v = (i < n) ? deg[i] : 0;
    s[t] = v;
    __syncthreads();
    #pragma unroll
    for (int off = 1; off < 256; off <<= 1) {
        int u = (t >= off) ? s[t - off] : 0;
        __syncthreads();
        s[t] += u;
        __syncthreads();
    }
    if (i < n) { rowptr[i] = blockOff + s[t] - v; cur[i] = 0; }
    if (blockIdx.x == gridDim.x - 1 && t == 255) rowptr[n] = blockOff + s[255];
}

__global__ void fill_csr_kernel(const int* __restrict__ src, const int* __restrict__ dst, int E,
                                const int* __restrict__ rowptr, int* __restrict__ cur,
                                int* __restrict__ col) {
    int i = blockIdx.x * blockDim.x + threadIdx.x;
    if (i >= E) return;
    int d = dst[i];
    int pos = rowptr[d] + atomicAdd(&cur[d], 1);
    col[pos] = src[i];
}

// ---------------- input-space aggregation (fp16 gather, fp32 acc) --------------
template <int C>
__global__ void aggregate_kernel(const __half* __restrict__ xs,
                                 const int* __restrict__ rowptr, const int* __restrict__ col,
                                 const float* __restrict__ dinv,
                                 __half* __restrict__ out, int ldo, int n)
{
    int node = (blockIdx.x * blockDim.x + threadIdx.x) >> 5;
    if (node >= n) return;
    int lane = threadIdx.x & 31;
    constexpr int F  = C / 32;
    constexpr int HV = F / 2;

    float acc[F];

    auto loadRow = [&](const __half* p, half2* h) {
        if constexpr (F == 2) {
            *(uint32_t*)h = *(const uint32_t*)p;
        } else if constexpr (F == 4) {
            *(uint2*)h = *(const uint2*)p;
        } else {
            *(uint4*)h = *(const uint4*)p;
        }
    };
    auto accRow = [&](const half2* h) {
        #pragma unroll
        for (int j = 0; j < HV; j++) {
            float2 f = __half22float2(h[j]);
            acc[2 * j] += f.x; acc[2 * j + 1] += f.y;
        }
    };

    {
        half2 h[HV];
        loadRow(xs + (size_t)node * C + lane * F, h);
        #pragma unroll
        for (int j = 0; j < HV; j++) {
            float2 f = __half22float2(h[j]);
            acc[2 * j] = f.x; acc[2 * j + 1] = f.y;
        }
    }

    int s = rowptr[node], e = rowptr[node + 1];
    int k = s;
    for (; k + 3 < e; k += 4) {
        half2 h0[HV], h1[HV], h2[HV], h3[HV];
        loadRow(xs + (size_t)col[k + 0] * C + lane * F, h0);
        loadRow(xs + (size_t)col[k + 1] * C + lane * F, h1);
        loadRow(xs + (size_t)col[k + 2] * C + lane * F, h2);
        loadRow(xs + (size_t)col[k + 3] * C + lane * F, h3);
        accRow(h0); accRow(h1); accRow(h2); accRow(h3);
    }
    for (; k < e; k++) {
        half2 h[HV];
        loadRow(xs + (size_t)col[k] * C + lane * F, h);
        accRow(h);
    }

    float dv = dinv[node];
    half2* orow = (half2*)(out + (size_t)node * ldo + lane * F);
    #pragma unroll
    for (int j = 0; j < HV; j++)
        orow[j] = __floats2half2_rn(dv * acc[2 * j], dv * acc[2 * j + 1]);
}

// ---------------- fp16 GEMM: 8 warps, warp tile 64x32, BK=64, 2-stage ----------
#define GEMM_AS 9216          // halfs per A stage (128*72)
#define GEMM_BS 8704          // halfs per B stage (64*136)
#define GEMM_STAGE (GEMM_AS + GEMM_BS)
#define GEMM_SMEM (2 * GEMM_STAGE * 2)   // bytes = 71680

__global__ __launch_bounds__(256) void gemm_h_kernel(
    const __half* __restrict__ A, const __half* __restrict__ B,
    __half* __restrict__ Ch, float* __restrict__ Cf,
    int M, int N, int K, int ldc, int kChunk, int atomicOut,
    const float* __restrict__ bias1, const float* __restrict__ bias2,
    __half* __restrict__ C2, int ld2, const float* __restrict__ dinv)
{
    extern __shared__ __half sm[];
    const int BK = 64;
    const int LDA = 72, LDB = 136;

    int tid  = threadIdx.x;
    int lane = tid & 31;
    int warp = tid >> 5;
    int warpM = (warp >> 2) * 64;
    int warpN = (warp & 3) * 32;
    int rowBase = blockIdx.y * 128;
    int colBase = blockIdx.x * 128;

    int kStart = blockIdx.z * kChunk;
    int kEnd   = min(K, kStart + kChunk);
    int ntiles = (kEnd - kStart) / BK;

    wmma::fragment<wmma::accumulator, 16, 16, 16, float> acc[4][2];
    #pragma unroll
    for (int m = 0; m < 4; m++)
        #pragma unroll
        for (int n = 0; n < 2; n++) wmma::fill_fragment(acc[m][n], 0.0f);

    uint32_t smBase = (uint32_t)__cvta_generic_to_shared(sm);

    auto issue = [&](int t, int s) {
        int k0 = kStart + t * BK;
        uint32_t asB = smBase + (uint32_t)(s * GEMM_STAGE) * 2u;
        uint32_t bsB = asB + (uint32_t)GEMM_AS * 2u;
        #pragma unroll
        for (int h = 0; h < 4; h++) {
            int c = tid + h * 256;
            int row = c >> 3, q = c & 7;
            int r = rowBase + row;
            bool ok = (r < M);
            const __half* src = A + (size_t)(ok ? r : 0) * K + k0 + q * 8;
            cp16(asB + (uint32_t)(row * LDA + q * 8) * 2u, src, ok);
        }
        #pragma unroll
        for (int h = 0; h < 4; h++) {
            int c = tid + h * 256;
            int row = c >> 4, q = c & 15;
            const __half* src = B + (size_t)(k0 + row) * N + colBase + q * 8;
            cp16(bsB + (uint32_t)(row * LDB + q * 8) * 2u, src, true);
        }
    };

    issue(0, 0);
    cp_commit();

    for (int t = 0; t < ntiles; t++) {
        if (t + 1 < ntiles) {
            issue(t + 1, (t + 1) & 1);
            cp_commit();
            cp_wait1g();
        } else {
            cp_wait0();
        }
        __syncthreads();

        const __half* as = sm + (t & 1) * GEMM_STAGE;
        const __half* bs = as + GEMM_AS;
        #pragma unroll
        for (int kk = 0; kk < BK; kk += 16) {
            wmma::fragment<wmma::matrix_a, 16, 16, 16, __half, wmma::row_major> af[4];
            wmma::fragment<wmma::matrix_b, 16, 16, 16, __half, wmma::row_major> bf[2];
            #pragma unroll
            for (int m = 0; m < 4; m++)
                wmma::load_matrix_sync(af[m], as + (warpM + 16 * m) * LDA + kk, LDA);
            #pragma unroll
            for (int n = 0; n < 2; n++)
                wmma::load_matrix_sync(bf[n], bs + kk * LDB + warpN + 16 * n, LDB);
            #pragma unroll
            for (int m = 0; m < 4; m++)
                #pragma unroll
                for (int n = 0; n < 2; n++)
                    wmma::mma_sync(acc[m][n], af[m], bf[n], acc[m][n]);
        }
        __syncthreads();
    }

    float* es = (float*)sm + warp * 320;
    #pragma unroll
    for (int m = 0; m < 4; m++) {
        #pragma unroll
        for (int n = 0; n < 2; n++) {
            wmma::store_matrix_sync(es, acc[m][n], 20, wmma::mem_row_major);
            __syncwarp();
            #pragma unroll
            for (int i = 0; i < 2; i++) {
                int r  = i * 8 + (lane >> 2);
                int c4 = (lane & 3) * 4;
                int gr = rowBase + warpM + 16 * m + r;
                int gc = colBase + warpN + 16 * n + c4;
                if (gr < M) {
                    float4 v = *(float4*)(es + r * 20 + c4);
                    if (Cf) {
                        float* cp = Cf + (size_t)gr * ldc + gc;
                        if (atomicOut) {
                            atomicAdd(cp + 0, v.x); atomicAdd(cp + 1, v.y);
                            atomicAdd(cp + 2, v.z); atomicAdd(cp + 3, v.w);
                        } else {
                            *(float4*)cp = v;
                        }
                    } else {
                        if (bias1) {
                            v.x += bias1[gc]; v.y += bias1[gc + 1];
                            v.z += bias1[gc + 2]; v.w += bias1[gc + 3];
                        }
                        if (bias2) {
                            v.x += bias2[gc]; v.y += bias2[gc + 1];
                            v.z += bias2[gc + 2]; v.w += bias2[gc + 3];
                        }
                        v.x = fmaxf(v.x, 0.f); v.y = fmaxf(v.y, 0.f);
                        v.z = fmaxf(v.z, 0.f); v.w = fmaxf(v.w, 0.f);
                        half2 h0 = __floats2half2_rn(v.x, v.y);
                        half2 h1 = __floats2half2_rn(v.z, v.w);
                        half2* cp = (half2*)(Ch + (size_t)gr * ldc + gc);
                        cp[0] = h0; cp[1] = h1;
                        if (C2) {
                            float dv = dinv[gr];
                            float2 f0 = __half22float2(h0);
                            float2 f1 = __half22float2(h1);
                            half2* c2 = (half2*)(C2 + (size_t)gr * ld2 + gc);
                            c2[0] = __floats2half2_rn(dv * f0.x, dv * f0.y);
                            c2[1] = __floats2half2_rn(dv * f1.x, dv * f1.y);
                        }
                    }
                }
            }
            __syncwarp();
        }
    }
}

// ---------------- softmax * x3 pooled mean + final projection (fused) ----------
__device__ __forceinline__ int lowerb(const int* a, int n, int key) {
    int lo = 0, hi = n;
    while (lo < hi) { int mid = (lo + hi) >> 1; if (a[mid] < key) lo = mid + 1; else hi = mid; }
    return lo;
}

__global__ void pool_final_kernel(const float* __restrict__ logits, const __half* __restrict__ x3,
                                  const int* __restrict__ batch,
                                  const float* __restrict__ fpa, const float* __restrict__ fga,
                                  const float* __restrict__ bfp, const float* __restrict__ bfg,
                                  const float* __restrict__ Wfc, const float* __restrict__ bfc,
                                  float* __restrict__ out, int n)
{
    __shared__ float sred[8 * 256];
    __shared__ float fsum[8];
    int g = blockIdx.x;
    int lane = threadIdx.x & 31;
    int w = threadIdx.x >> 5;

    int start = lowerb(batch, n, g);
    int end   = lowerb(batch, n, g + 1);

    float acc[8];
    #pragma unroll
    for (int j = 0; j < 8; j++) acc[j] = 0.f;

    for (int node = start + w; node < end; node += 8) {
        const float4* lr = (const float4*)(logits + (size_t)node * 256 + lane * 8);
        float4 a0 = lr[0], a1 = lr[1];
        float a[8] = {a0.x, a0.y, a0.z, a0.w, a1.x, a1.y, a1.z, a1.w};
        float m = a[0];
        #pragma unroll
        for (int j = 1; j < 8; j++) m = fmaxf(m, a[j]);
        #pragma unroll
        for (int off = 16; off > 0; off >>= 1) m = fmaxf(m, __shfl_xor_sync(0xFFFFFFFFu, m, off));
        float s = 0.f;
        #pragma unroll
        for (int j = 0; j < 8; j++) { a[j] = __expf(a[j] - m); s += a[j]; }
        #pragma unroll
        for (int off = 16; off > 0; off >>= 1) s += __shfl_xor_sync(0xFFFFFFFFu, s, off);
        float inv = 1.f / s;

        half2 hx[4];
        *(uint4*)hx = *(const uint4*)(x3 + (size_t)node * 256 + lane * 8);
        #pragma unroll
        for (int j = 0; j < 4; j++) {
            float2 f = __half22float2(hx[j]);
            acc[2 * j]     += a[2 * j]     * inv * f.x;
            acc[2 * j + 1] += a[2 * j + 1] * inv * f.y;
        }
    }

    #pragma unroll
    for (int j = 0; j < 8; j++) sred[w * 256 + lane * 8 + j] = acc[j];
    __syncthreads();

    int t = threadIdx.x;
    float v = 0.f;
    #pragma unroll
    for (int ww = 0; ww < 8; ww++) v += sred[ww * 256 + t];
    float invc = 1.f / fmaxf((float)(end - start), 1.f);
    size_t o = (size_t)g * 256 + t;
    float pv = v * invc
             + fmaxf(fpa[o] + bfp[t], 0.f)
             + fmaxf(fga[o] + bfg[t], 0.f);
    float term = pv * Wfc[t];

    #pragma unroll
    for (int off = 16; off > 0; off >>= 1) term += __shfl_xor_sync(0xFFFFFFFFu, term, off);
    if (lane == 0) fsum[w] = term;
    __syncthreads();
    if (t == 0) {
        float ssum = 0.f;
        #pragma unroll
        for (int ww = 0; ww < 8; ww++) ssum += fsum[ww];
        out[g] = ssum + bfc[0];
    }
}

// ---------------- host launcher -------------------------------------------------
extern "C" void kernel_launch(void* const* d_in, const int* in_sizes, int n_in,
                              void* d_out, int out_size)
{
    const float* x    = (const float*)d_in[0];
    const void*  eraw = d_in[1];
    const void*  braw = d_in[2];
    const float* fpf  = (const float*)d_in[3];
    const float* fgf  = (const float*)d_in[4];
    const float* W1   = (const float*)d_in[5];  const float* b1  = (const float*)d_in[6];
    const float* W2   = (const float*)d_in[7];  const float* b2  = (const float*)d_in[8];
    const float* W3   = (const float*)d_in[9];  const float* b3  = (const float*)d_in[10];
    const float* Wr1  = (const float*)d_in[11]; const float* br1 = (const float*)d_in[12];
    const float* Wr2  = (const float*)d_in[13]; const float* br2 = (const float*)d_in[14];
    const float* Wfp  = (const float*)d_in[15]; const float* bfp = (const float*)d_in[16];
    const float* Wfg  = (const float*)d_in[17]; const float* bfg = (const float*)d_in[18];
    const float* attn_W = (const float*)d_in[19];
    const float* Wfc  = (const float*)d_in[20]; const float* bfc = (const float*)d_in[21];
    float* out = (float*)d_out;

    int N = in_sizes[0] / 64;
    int E = in_sizes[1] / 2;
    int B = in_sizes[3] / 2048;

    __half *xs0, *A1, *A2, *xs1, *A3, *xs2, *x3;
    __half *w1r, *w2s, *w3s, *wattn, *fph, *wfph, *fgp, *wfgp;
    float *work, *dinv, *fp, *fg;
    int *eidx, *batch, *deg, *rowptr, *bsum, *cur, *col, *flag;
    cudaGetSymbolAddress((void**)&eidx,   g_eidx);
    cudaGetSymbolAddress((void**)&batch,  g_batch);
    cudaGetSymbolAddress((void**)&deg,    g_deg);
    cudaGetSymbolAddress((void**)&rowptr, g_rowptr);
    cudaGetSymbolAddress((void**)&bsum,   g_bsum);
    cudaGetSymbolAddress((void**)&cur,    g_cur);
    cudaGetSymbolAddress((void**)&col,    g_col);
    cudaGetSymbolAddress((void**)&flag,   g_flag);
    cudaGetSymbolAddress((void**)&dinv,   g_dinv);
    cudaGetSymbolAddress((void**)&xs0,    g_xs0);
    cudaGetSymbolAddress((void**)&A1,     g_A1);
    cudaGetSymbolAddress((void**)&A2,     g_A2);
    cudaGetSymbolAddress((void**)&xs1,    g_xs1);
    cudaGetSymbolAddress((void**)&A3,     g_A3);
    cudaGetSymbolAddress((void**)&xs2,    g_xs2);
    cudaGetSymbolAddress((void**)&x3,     g_x3);
    cudaGetSymbolAddress((void**)&work,   g_work);
    cudaGetSymbolAddress((void**)&w1r,    g_w1r);
    cudaGetSymbolAddress((void**)&w2s,    g_w2s);
    cudaGetSymbolAddress((void**)&w3s,    g_w3s);
    cudaGetSymbolAddress((void**)&wattn,  g_wattn);
    cudaGetSymbolAddress((void**)&fph,    g_fph);
    cudaGetSymbolAddress((void**)&wfph,   g_wfph);
    cudaGetSymbolAddress((void**)&fgp,    g_fgp);
    cudaGetSymbolAddress((void**)&wfgp,   g_wfgp);
    cudaGetSymbolAddress((void**)&fp,     g_fp);
    cudaGetSymbolAddress((void**)&fg,     g_fg);

    static int attrSet = 0;
    if (!attrSet) {
        cudaFuncSetAttribute(gemm_h_kernel, cudaFuncAttributeMaxDynamicSharedMemorySize, GEMM_SMEM);
        attrSet = 1;
    }

    cudaMemsetAsync(deg, 0, N * sizeof(int));
    cudaMemsetAsync(fp,  0, (size_t)B * 256 * sizeof(float));

    // dtype detect + combined edge/batch conversion + degree
    detect_kernel<<<1, 32>>>((const unsigned int*)eraw, flag);
    cvt_all_kernel<<<(E + N + 255) / 256, 256>>>(eraw, E, braw, N, flag, eidx, deg, batch);
    const int* srcA = eidx;
    const int* dstA = eidx + E;

    // two-phase scan (dinv + xs0 fused in p1; bsum prefix + cur zero in p2)
    int nb = (N + 255) / 256;
    scan_p1_kernel<<<nb, 256>>>(deg, dinv, bsum, x, xs0, N);
    scan_p2_kernel<<<nb, 256>>>(deg, bsum, rowptr, cur, N, nb);
    fill_csr_kernel<<<(E + 255) / 256, 256>>>(srcA, dstA, E, rowptr, cur, col);

    prep_kernel<<<(PREP_TOTAL + 255) / 256, 256>>>(
        W1, W2, Wr1, W3, Wr2, attn_W, fpf, Wfp, fgf, Wfg,
        w1r, w2s, w3s, wattn, fph, wfph, fgp, wfgp);

    int aggBlocks = (N * 32 + 255) / 256;
    int gy = (N + 127) / 128;

    // fp / fg (fp16; fp split-K 8 with fp32 atomic accum; kChunk multiples of 64)
    gemm_h_kernel<<<dim3(2, (B + 127) / 128, 8), 256, GEMM_SMEM>>>(
        fph, wfph, nullptr, fp, B, 256, 2048, 256, 256, 1,
        nullptr, nullptr, nullptr, 0, nullptr);
    gemm_h_kernel<<<dim3(2, (B + 127) / 128, 1), 256, GEMM_SMEM>>>(
        fgp, wfgp, nullptr, fg, B, 256, 192, 256, 192, 0,
        nullptr, nullptr, nullptr, 0, nullptr);

    // Layer 1 (K=64)
    aggregate_kernel<64><<<aggBlocks, 256>>>(xs0, rowptr, col, dinv, A1, 64, N);
    gemm_h_kernel<<<dim3(1, gy), 256, GEMM_SMEM>>>(
        A1, w1r, A2 + 128, nullptr, N, 128, 64, 256, 64, 0,
        b1, nullptr, xs1, 128, dinv);

    // Layer 2 (K=256)
    aggregate_kernel<128><<<aggBlocks, 256>>>(xs1, rowptr, col, dinv, A2, 256, N);
    gemm_h_kernel<<<dim3(2, gy), 256, GEMM_SMEM>>>(
        A2, w2s, A3 + 256, nullptr, N, 256, 256, 512, 256, 0,
        b2, br1, xs2, 256, dinv);

    // Layer 3 (K=512)
    aggregate_kernel<256><<<aggBlocks, 256>>>(xs2, rowptr, col, dinv, A3, 512, N);
    gemm_h_kernel<<<dim3(2, gy), 256, GEMM_SMEM>>>(
        A3, w3s, x3, nullptr, N, 256, 512, 256, 512, 0,
        b3, br2, nullptr, 0, nullptr);

    // Attention logits (fp32 out, K=256)
    gemm_h_kernel<<<dim3(2, gy), 256, GEMM_SMEM>>>(
        x3, wattn, nullptr, work, N, 256, 256, 256, 256, 0,
        nullptr, nullptr, nullptr, 0, nullptr);

    // fused softmax-pool + final projection
    pool_final_kernel<<<B, 256>>>(work, x3, batch, fp, fg, bfp, bfg, Wfc, bfc, out, N);
}